// round 3
// baseline (speedup 1.0000x reference)
#include <cuda_runtime.h>

#define NQ 10
#define DEPTH 6
#define NF 1024
#define NC 10
#define MAXB 8192

typedef unsigned long long u64;

// Precomputed Rot matrices: [l][q] -> two float4: (u00r,u00i,u01r,u01i),(u10r,u10i,u11r,u11i)
__device__ float4 g_rot4[DEPTH * NQ * 2];
// Precomputed half-angle trig per sample/qubit: (cos, sin)
__device__ float2 g_trig[MAXB * NQ];

// ---------- f32x2 packed helpers ----------
__device__ __forceinline__ u64 pk(float x, float y) {
    u64 u; asm("mov.b64 %0,{%1,%2};" : "=l"(u) : "f"(x), "f"(y)); return u;
}
__device__ __forceinline__ u64 dup2(float x) { return pk(x, x); }
__device__ __forceinline__ void unpk(u64 u, float& x, float& y) {
    asm("mov.b64 {%0,%1},%2;" : "=f"(x), "=f"(y) : "l"(u));
}
__device__ __forceinline__ u64 fma2(u64 a, u64 b, u64 c) {
    u64 d; asm("fma.rn.f32x2 %0,%1,%2,%3;" : "=l"(d) : "l"(a), "l"(b), "l"(c)); return d;
}
__device__ __forceinline__ u64 mul2(u64 a, u64 b) {
    u64 d; asm("mul.rn.f32x2 %0,%1,%2;" : "=l"(d) : "l"(a), "l"(b)); return d;
}
__device__ __forceinline__ u64 add2(u64 a, u64 b) {
    u64 d; asm("add.rn.f32x2 %0,%1,%2;" : "=l"(d) : "l"(a), "l"(b)); return d;
}
__device__ __forceinline__ u64 neg2(u64 a) { return a ^ 0x8000000080000000ULL; }

// ---------- rot matrix build (device-side helper, run by one extra proj block) ----------
__device__ __forceinline__ void build_rot_one(const float* __restrict__ w, int t) {
    float phi = w[t * 3 + 0], theta = w[t * 3 + 1], omega = w[t * 3 + 2];
    float c, s;
    sincosf(0.5f * theta, &s, &c);
    float sp, cp, sm, cm;
    sincosf(-0.5f * (phi + omega), &sp, &cp);  // ep
    sincosf(-0.5f * (phi - omega), &sm, &cm);  // em
    g_rot4[t * 2 + 0] = make_float4(cp * c, sp * c, -cm * s, sm * s);   // u00, u01
    g_rot4[t * 2 + 1] = make_float4(cm * s, sm * s, cp * c, -sp * c);   // u10, u11
}

// one warp per sample: 10 dot products (len 1024) -> tanh -> half-angle trig
// last block builds the rot matrices instead.
__global__ __launch_bounds__(256) void proj_kernel(const float* __restrict__ x,
                                                   const float* __restrict__ Wp,
                                                   const float* __restrict__ w, int B) {
    if (blockIdx.x == gridDim.x - 1) {
        int t = threadIdx.x;
        if (t < DEPTH * NQ) build_rot_one(w, t);
        return;
    }
    int warp = threadIdx.x >> 5, lane = threadIdx.x & 31;
    int b = blockIdx.x * 8 + warp;
    if (b >= B) return;
    const float4* xv = (const float4*)(x + (size_t)b * NF);
    float acc[NQ];
#pragma unroll
    for (int q = 0; q < NQ; q++) acc[q] = 0.f;
#pragma unroll
    for (int it = 0; it < 8; it++) {
        float4 xx = xv[it * 32 + lane];
#pragma unroll
        for (int q = 0; q < NQ; q++) {
            float4 ww = __ldg(&((const float4*)(Wp + q * NF))[it * 32 + lane]);
            acc[q] += xx.x * ww.x + xx.y * ww.y + xx.z * ww.z + xx.w * ww.w;
        }
    }
#pragma unroll
    for (int off = 16; off > 0; off >>= 1)
#pragma unroll
        for (int q = 0; q < NQ; q++) acc[q] += __shfl_xor_sync(0xffffffffu, acc[q], off);
    if (lane < NQ) {
        float v = acc[0];
#pragma unroll
        for (int q = 1; q < NQ; q++)
            if (lane == q) v = acc[q];
        float half = tanhf(v) * 0.78539816339744831f;  // (pi/2)/2
        float cc, ss;
        sincosf(half, &ss, &cc);
        g_trig[b * NQ + lane] = make_float2(cc, ss);
    }
}

// CNOT ring (range R) on packed u64 statevector.
// qubit q = bit q of amplitude index m = r*32 + lane (lane bits q0..4, reg bits q5..9)
template <int R>
__device__ __forceinline__ void cnot_layer(u64 (&sr)[32], u64 (&si)[32], int lane) {
#pragma unroll
    for (int i = 0; i < NQ; i++) {
        const int c = i;
        const int t = (i + R) % NQ;
        if (c < 5 && t < 5) {
            bool ctrl = (lane >> c) & 1;
#pragma unroll
            for (int r = 0; r < 32; r++) {
                u64 pr_ = __shfl_xor_sync(0xffffffffu, sr[r], 1 << t);
                u64 pi_ = __shfl_xor_sync(0xffffffffu, si[r], 1 << t);
                sr[r] = ctrl ? pr_ : sr[r];
                si[r] = ctrl ? pi_ : si[r];
            }
        } else if (c < 5 && t >= 5) {
            const int tb = 1 << (t - 5);
            bool ctrl = (lane >> c) & 1;
#pragma unroll
            for (int r0 = 0; r0 < 32; r0++)
                if (!(r0 & tb)) {
                    const int r1 = r0 | tb;
                    u64 t0 = sr[r0], t1 = si[r0];
                    sr[r0] = ctrl ? sr[r1] : sr[r0];
                    si[r0] = ctrl ? si[r1] : si[r0];
                    sr[r1] = ctrl ? t0 : sr[r1];
                    si[r1] = ctrl ? t1 : si[r1];
                }
        } else if (c >= 5 && t < 5) {
            const int cb = 1 << (c - 5);
#pragma unroll
            for (int r = 0; r < 32; r++)
                if (r & cb) {
                    sr[r] = __shfl_xor_sync(0xffffffffu, sr[r], 1 << t);
                    si[r] = __shfl_xor_sync(0xffffffffu, si[r], 1 << t);
                }
        } else {
            const int cb = 1 << (c - 5), tb = 1 << (t - 5);
#pragma unroll
            for (int r0 = 0; r0 < 32; r0++)
                if ((r0 & cb) && !(r0 & tb)) {
                    const int r1 = r0 | tb;
                    u64 tmp = sr[r0]; sr[r0] = sr[r1]; sr[r1] = tmp;
                    tmp = si[r0]; si[r0] = si[r1]; si[r1] = tmp;
                }
        }
    }
}

// one warp simulates TWO samples (A = low f32, B = high f32 of every packed value)
__global__ __launch_bounds__(128, 2) void vqc2_kernel(const float* __restrict__ Wout,
                                                      const float* __restrict__ bout,
                                                      float* __restrict__ out, int B) {
    const int warp = threadIdx.x >> 5, lane = threadIdx.x & 31;
    const int pair = blockIdx.x * 4 + warp;
    const int bA = 2 * pair;
    if (bA >= B) return;
    const int bB = bA + 1;
    const bool hasB = (bB < B);
    const int bBc = hasB ? bB : bA;

    // ---- packed half-angle trig ----
    u64 pc[NQ], ps[NQ];
#pragma unroll
    for (int q = 0; q < NQ; q++) {
        float2 vA = g_trig[bA * NQ + q];
        float2 vB = g_trig[bBc * NQ + q];
        pc[q] = pk(vA.x, vB.x);
        ps[q] = pk(vA.y, vB.y);
    }

    // ---- init: RY product state ----
    u64 pl = ((lane >> 0) & 1) ? ps[0] : pc[0];
#pragma unroll
    for (int j = 1; j < 5; j++) pl = mul2(pl, ((lane >> j) & 1) ? ps[j] : pc[j]);
    u64 sr[32], si[32];
#pragma unroll
    for (int r = 0; r < 32; r++) {
        u64 v = pl;
#pragma unroll
        for (int j = 0; j < 5; j++) v = mul2(v, ((r >> j) & 1) ? ps[5 + j] : pc[5 + j]);
        sr[r] = v;
        si[r] = 0ULL;
    }

    // ---- layers ----
#pragma unroll 1
    for (int l = 0; l < DEPTH; l++) {
#pragma unroll
        for (int q = 0; q < NQ; q++) {
            float4 A = __ldg(&g_rot4[(l * NQ + q) * 2]);       // u00, u01
            float4 Bm = __ldg(&g_rot4[(l * NQ + q) * 2 + 1]);  // u10, u11
            if (q >= 5) {
                u64 c00r = dup2(A.x), c00i = dup2(A.y), c00in = dup2(-A.y);
                u64 c01r = dup2(A.z), c01i = dup2(A.w), c01in = dup2(-A.w);
                u64 c10r = dup2(Bm.x), c10i = dup2(Bm.y), c10in = dup2(-Bm.y);
                u64 c11r = dup2(Bm.z), c11i = dup2(Bm.w), c11in = dup2(-Bm.w);
                const int jb = 1 << (q - 5);
#pragma unroll
                for (int r0 = 0; r0 < 32; r0++)
                    if (!(r0 & jb)) {
                        const int r1 = r0 | jb;
                        u64 a0r = sr[r0], a0i = si[r0];
                        u64 a1r = sr[r1], a1i = si[r1];
                        u64 t;
                        t = mul2(c01in, a1i); t = fma2(c01r, a1r, t); t = fma2(c00in, a0i, t);
                        sr[r0] = fma2(c00r, a0r, t);
                        t = mul2(c01i, a1r); t = fma2(c01r, a1i, t); t = fma2(c00i, a0r, t);
                        si[r0] = fma2(c00r, a0i, t);
                        t = mul2(c11in, a1i); t = fma2(c11r, a1r, t); t = fma2(c10in, a0i, t);
                        sr[r1] = fma2(c10r, a0r, t);
                        t = mul2(c11i, a1r); t = fma2(c11r, a1i, t); t = fma2(c10i, a0r, t);
                        si[r1] = fma2(c10r, a0i, t);
                    }
            } else {
                bool hi = (lane >> q) & 1;
                float car = hi ? Bm.z : A.x, cai = hi ? Bm.w : A.y;
                float cbr = hi ? Bm.x : A.z, cbi = hi ? Bm.y : A.w;
                u64 Car = dup2(car), Cai = dup2(cai), Cain = dup2(-cai);
                u64 Cbr = dup2(cbr), Cbi = dup2(cbi), Cbin = dup2(-cbi);
#pragma unroll
                for (int r = 0; r < 32; r++) {
                    u64 pr_ = __shfl_xor_sync(0xffffffffu, sr[r], 1 << q);
                    u64 pi_ = __shfl_xor_sync(0xffffffffu, si[r], 1 << q);
                    u64 mr = sr[r], mi = si[r];
                    u64 t;
                    t = mul2(Cbin, pi_); t = fma2(Cbr, pr_, t); t = fma2(Cain, mi, t);
                    sr[r] = fma2(Car, mr, t);
                    t = mul2(Cbi, pr_); t = fma2(Cbr, pi_, t); t = fma2(Cai, mr, t);
                    si[r] = fma2(Car, mi, t);
                }
            }
        }
        switch (l) {
            case 0: cnot_layer<1>(sr, si, lane); break;
            case 1: cnot_layer<2>(sr, si, lane); break;
            case 2: cnot_layer<3>(sr, si, lane); break;
            case 3: cnot_layer<4>(sr, si, lane); break;
            case 4: cnot_layer<5>(sr, si, lane); break;
            default: cnot_layer<6>(sr, si, lane); break;
        }
    }

    // ---- Z expvals (packed) ----
    u64 S = 0ULL, T0 = 0ULL, T1 = 0ULL, T2 = 0ULL, T3 = 0ULL, T4 = 0ULL;
#pragma unroll
    for (int r = 0; r < 32; r++) {
        u64 p = fma2(sr[r], sr[r], mul2(si[r], si[r]));
        u64 np = neg2(p);
        S = add2(S, p);
        T0 = add2(T0, (r & 1) ? np : p);
        T1 = add2(T1, (r & 2) ? np : p);
        T2 = add2(T2, (r & 4) ? np : p);
        T3 = add2(T3, (r & 8) ? np : p);
        T4 = add2(T4, (r & 16) ? np : p);
    }
    u64 e[NQ];
#pragma unroll
    for (int q = 0; q < 5; q++) e[q] = ((lane >> q) & 1) ? neg2(S) : S;
    e[5] = T0; e[6] = T1; e[7] = T2; e[8] = T3; e[9] = T4;
#pragma unroll
    for (int off = 16; off > 0; off >>= 1)
#pragma unroll
        for (int q = 0; q < NQ; q++)
            e[q] = add2(e[q], __shfl_xor_sync(0xffffffffu, e[q], off));

    // ---- linear head for both samples ----
    if (lane < NC) {
        float eA[NQ], eB[NQ];
#pragma unroll
        for (int q = 0; q < NQ; q++) unpk(e[q], eA[q], eB[q]);
        float oA = __ldg(&bout[lane]);
        float oB = oA;
#pragma unroll
        for (int q = 0; q < NQ; q++) {
            float w = __ldg(&Wout[lane * NQ + q]);
            oA += eA[q] * w;
            oB += eB[q] * w;
        }
        out[(size_t)bA * NC + lane] = oA;
        if (hasB) out[(size_t)bB * NC + lane] = oB;
    }
}

extern "C" void kernel_launch(void* const* d_in, const int* in_sizes, int n_in,
                              void* d_out, int out_size) {
    const float* x = (const float*)d_in[0];        // (B, 1024)
    const float* W_proj = (const float*)d_in[1];   // (10, 1024)
    const float* weights = (const float*)d_in[2];  // (6, 10, 3)
    const float* W_out = (const float*)d_in[3];    // (10, 10)
    const float* b_out = (const float*)d_in[4];    // (10,)
    float* out = (float*)d_out;                    // (B, 10)

    int B = in_sizes[0] / NF;
    int nblk = (B + 7) / 8;
    int npairs = (B + 1) / 2;
    int nblk2 = (npairs + 3) / 4;

    proj_kernel<<<nblk + 1, 256>>>(x, W_proj, weights, B);
    vqc2_kernel<<<nblk2, 128>>>(W_out, b_out, out, B);
}

// round 4
// speedup vs baseline: 1.0047x; 1.0047x over previous
#include <cuda_runtime.h>

#define NQ 10
#define DEPTH 6
#define NF 1024
#define NC 10
#define MAXB 8192

typedef unsigned long long u64;

// Precomputed Rot matrices: [l][q] -> two float4: (u00r,u00i,u01r,u01i),(u10r,u10i,u11r,u11i)
__device__ float4 g_rot4[DEPTH * NQ * 2];
// Precomputed half-angle trig per sample/qubit: (cos, sin)
__device__ float2 g_trig[MAXB * NQ];

// ---------- f32x2 packed helpers ----------
__device__ __forceinline__ u64 pk(float x, float y) {
    u64 u; asm("mov.b64 %0,{%1,%2};" : "=l"(u) : "f"(x), "f"(y)); return u;
}
__device__ __forceinline__ u64 dup2(float x) { return pk(x, x); }
__device__ __forceinline__ void unpk(u64 u, float& x, float& y) {
    asm("mov.b64 {%0,%1},%2;" : "=f"(x), "=f"(y) : "l"(u));
}
__device__ __forceinline__ u64 fma2(u64 a, u64 b, u64 c) {
    u64 d; asm("fma.rn.f32x2 %0,%1,%2,%3;" : "=l"(d) : "l"(a), "l"(b), "l"(c)); return d;
}
__device__ __forceinline__ u64 mul2(u64 a, u64 b) {
    u64 d; asm("mul.rn.f32x2 %0,%1,%2;" : "=l"(d) : "l"(a), "l"(b)); return d;
}
__device__ __forceinline__ u64 add2(u64 a, u64 b) {
    u64 d; asm("add.rn.f32x2 %0,%1,%2;" : "=l"(d) : "l"(a), "l"(b)); return d;
}
__device__ __forceinline__ u64 neg2(u64 a) { return a ^ 0x8000000080000000ULL; }

// ---------- rot matrix build (device-side helper, run by one extra proj block) ----------
__device__ __forceinline__ void build_rot_one(const float* __restrict__ w, int t) {
    float phi = w[t * 3 + 0], theta = w[t * 3 + 1], omega = w[t * 3 + 2];
    float c, s;
    sincosf(0.5f * theta, &s, &c);
    float sp, cp, sm, cm;
    sincosf(-0.5f * (phi + omega), &sp, &cp);  // ep
    sincosf(-0.5f * (phi - omega), &sm, &cm);  // em
    g_rot4[t * 2 + 0] = make_float4(cp * c, sp * c, -cm * s, sm * s);   // u00, u01
    g_rot4[t * 2 + 1] = make_float4(cm * s, sm * s, cp * c, -sp * c);   // u10, u11
}

// one warp per sample: 10 dot products (len 1024) -> tanh -> half-angle trig
// last block builds the rot matrices instead.
__global__ __launch_bounds__(256) void proj_kernel(const float* __restrict__ x,
                                                   const float* __restrict__ Wp,
                                                   const float* __restrict__ w, int B) {
    if (blockIdx.x == gridDim.x - 1) {
        int t = threadIdx.x;
        if (t < DEPTH * NQ) build_rot_one(w, t);
        return;
    }
    int warp = threadIdx.x >> 5, lane = threadIdx.x & 31;
    int b = blockIdx.x * 8 + warp;
    if (b >= B) return;
    const float4* xv = (const float4*)(x + (size_t)b * NF);
    float acc[NQ];
#pragma unroll
    for (int q = 0; q < NQ; q++) acc[q] = 0.f;
#pragma unroll
    for (int it = 0; it < 8; it++) {
        float4 xx = xv[it * 32 + lane];
#pragma unroll
        for (int q = 0; q < NQ; q++) {
            float4 ww = __ldg(&((const float4*)(Wp + q * NF))[it * 32 + lane]);
            acc[q] += xx.x * ww.x + xx.y * ww.y + xx.z * ww.z + xx.w * ww.w;
        }
    }
#pragma unroll
    for (int off = 16; off > 0; off >>= 1)
#pragma unroll
        for (int q = 0; q < NQ; q++) acc[q] += __shfl_xor_sync(0xffffffffu, acc[q], off);
    if (lane < NQ) {
        float v = acc[0];
#pragma unroll
        for (int q = 1; q < NQ; q++)
            if (lane == q) v = acc[q];
        float half = tanhf(v) * 0.78539816339744831f;  // (pi/2)/2
        float cc, ss;
        sincosf(half, &ss, &cc);
        g_trig[b * NQ + lane] = make_float2(cc, ss);
    }
}

// CNOT ring (range R) on packed u64 statevector.
// qubit q = bit q of amplitude index m = r*32 + lane (lane bits q0..4, reg bits q5..9)
template <int R>
__device__ __forceinline__ void cnot_layer(u64 (&sr)[32], u64 (&si)[32], int lane) {
#pragma unroll
    for (int i = 0; i < NQ; i++) {
        const int c = i;
        const int t = (i + R) % NQ;
        if (c < 5 && t < 5) {
            bool ctrl = (lane >> c) & 1;
#pragma unroll
            for (int r = 0; r < 32; r++) {
                u64 pr_ = __shfl_xor_sync(0xffffffffu, sr[r], 1 << t);
                u64 pi_ = __shfl_xor_sync(0xffffffffu, si[r], 1 << t);
                sr[r] = ctrl ? pr_ : sr[r];
                si[r] = ctrl ? pi_ : si[r];
            }
        } else if (c < 5 && t >= 5) {
            const int tb = 1 << (t - 5);
            bool ctrl = (lane >> c) & 1;
#pragma unroll
            for (int r0 = 0; r0 < 32; r0++)
                if (!(r0 & tb)) {
                    const int r1 = r0 | tb;
                    u64 t0 = sr[r0], t1 = si[r0];
                    sr[r0] = ctrl ? sr[r1] : sr[r0];
                    si[r0] = ctrl ? si[r1] : si[r0];
                    sr[r1] = ctrl ? t0 : sr[r1];
                    si[r1] = ctrl ? t1 : si[r1];
                }
        } else if (c >= 5 && t < 5) {
            const int cb = 1 << (c - 5);
#pragma unroll
            for (int r = 0; r < 32; r++)
                if (r & cb) {
                    sr[r] = __shfl_xor_sync(0xffffffffu, sr[r], 1 << t);
                    si[r] = __shfl_xor_sync(0xffffffffu, si[r], 1 << t);
                }
        } else {
            const int cb = 1 << (c - 5), tb = 1 << (t - 5);
#pragma unroll
            for (int r0 = 0; r0 < 32; r0++)
                if ((r0 & cb) && !(r0 & tb)) {
                    const int r1 = r0 | tb;
                    u64 tmp = sr[r0]; sr[r0] = sr[r1]; sr[r1] = tmp;
                    tmp = si[r0]; si[r0] = si[r1]; si[r1] = tmp;
                }
        }
    }
}

// one warp simulates TWO samples (A = low f32, B = high f32 of every packed value)
__global__ __launch_bounds__(128, 2) void vqc2_kernel(const float* __restrict__ Wout,
                                                      const float* __restrict__ bout,
                                                      float* __restrict__ out, int B) {
    const int warp = threadIdx.x >> 5, lane = threadIdx.x & 31;
    const int pair = blockIdx.x * 4 + warp;
    const int bA = 2 * pair;
    if (bA >= B) return;
    const int bB = bA + 1;
    const bool hasB = (bB < B);
    const int bBc = hasB ? bB : bA;

    // ---- packed half-angle trig ----
    u64 pc[NQ], ps[NQ];
#pragma unroll
    for (int q = 0; q < NQ; q++) {
        float2 vA = g_trig[bA * NQ + q];
        float2 vB = g_trig[bBc * NQ + q];
        pc[q] = pk(vA.x, vB.x);
        ps[q] = pk(vA.y, vB.y);
    }

    // ---- init: RY product state ----
    u64 pl = ((lane >> 0) & 1) ? ps[0] : pc[0];
#pragma unroll
    for (int j = 1; j < 5; j++) pl = mul2(pl, ((lane >> j) & 1) ? ps[j] : pc[j]);
    u64 sr[32], si[32];
#pragma unroll
    for (int r = 0; r < 32; r++) {
        u64 v = pl;
#pragma unroll
        for (int j = 0; j < 5; j++) v = mul2(v, ((r >> j) & 1) ? ps[5 + j] : pc[5 + j]);
        sr[r] = v;
        si[r] = 0ULL;
    }

    // ---- layers ----
#pragma unroll 1
    for (int l = 0; l < DEPTH; l++) {
#pragma unroll
        for (int q = 0; q < NQ; q++) {
            float4 A = __ldg(&g_rot4[(l * NQ + q) * 2]);       // u00, u01
            float4 Bm = __ldg(&g_rot4[(l * NQ + q) * 2 + 1]);  // u10, u11
            if (q >= 5) {
                u64 c00r = dup2(A.x), c00i = dup2(A.y), c00in = dup2(-A.y);
                u64 c01r = dup2(A.z), c01i = dup2(A.w), c01in = dup2(-A.w);
                u64 c10r = dup2(Bm.x), c10i = dup2(Bm.y), c10in = dup2(-Bm.y);
                u64 c11r = dup2(Bm.z), c11i = dup2(Bm.w), c11in = dup2(-Bm.w);
                const int jb = 1 << (q - 5);
#pragma unroll
                for (int r0 = 0; r0 < 32; r0++)
                    if (!(r0 & jb)) {
                        const int r1 = r0 | jb;
                        u64 a0r = sr[r0], a0i = si[r0];
                        u64 a1r = sr[r1], a1i = si[r1];
                        u64 t;
                        t = mul2(c01in, a1i); t = fma2(c01r, a1r, t); t = fma2(c00in, a0i, t);
                        sr[r0] = fma2(c00r, a0r, t);
                        t = mul2(c01i, a1r); t = fma2(c01r, a1i, t); t = fma2(c00i, a0r, t);
                        si[r0] = fma2(c00r, a0i, t);
                        t = mul2(c11in, a1i); t = fma2(c11r, a1r, t); t = fma2(c10in, a0i, t);
                        sr[r1] = fma2(c10r, a0r, t);
                        t = mul2(c11i, a1r); t = fma2(c11r, a1i, t); t = fma2(c10i, a0r, t);
                        si[r1] = fma2(c10r, a0i, t);
                    }
            } else {
                bool hi = (lane >> q) & 1;
                float car = hi ? Bm.z : A.x, cai = hi ? Bm.w : A.y;
                float cbr = hi ? Bm.x : A.z, cbi = hi ? Bm.y : A.w;
                u64 Car = dup2(car), Cai = dup2(cai), Cain = dup2(-cai);
                u64 Cbr = dup2(cbr), Cbi = dup2(cbi), Cbin = dup2(-cbi);
#pragma unroll
                for (int r = 0; r < 32; r++) {
                    u64 pr_ = __shfl_xor_sync(0xffffffffu, sr[r], 1 << q);
                    u64 pi_ = __shfl_xor_sync(0xffffffffu, si[r], 1 << q);
                    u64 mr = sr[r], mi = si[r];
                    u64 t;
                    t = mul2(Cbin, pi_); t = fma2(Cbr, pr_, t); t = fma2(Cain, mi, t);
                    sr[r] = fma2(Car, mr, t);
                    t = mul2(Cbi, pr_); t = fma2(Cbr, pi_, t); t = fma2(Cai, mr, t);
                    si[r] = fma2(Car, mi, t);
                }
            }
        }
        switch (l) {
            case 0: cnot_layer<1>(sr, si, lane); break;
            case 1: cnot_layer<2>(sr, si, lane); break;
            case 2: cnot_layer<3>(sr, si, lane); break;
            case 3: cnot_layer<4>(sr, si, lane); break;
            case 4: cnot_layer<5>(sr, si, lane); break;
            default: cnot_layer<6>(sr, si, lane); break;
        }
    }

    // ---- Z expvals (packed) ----
    u64 S = 0ULL, T0 = 0ULL, T1 = 0ULL, T2 = 0ULL, T3 = 0ULL, T4 = 0ULL;
#pragma unroll
    for (int r = 0; r < 32; r++) {
        u64 p = fma2(sr[r], sr[r], mul2(si[r], si[r]));
        u64 np = neg2(p);
        S = add2(S, p);
        T0 = add2(T0, (r & 1) ? np : p);
        T1 = add2(T1, (r & 2) ? np : p);
        T2 = add2(T2, (r & 4) ? np : p);
        T3 = add2(T3, (r & 8) ? np : p);
        T4 = add2(T4, (r & 16) ? np : p);
    }
    u64 e[NQ];
#pragma unroll
    for (int q = 0; q < 5; q++) e[q] = ((lane >> q) & 1) ? neg2(S) : S;
    e[5] = T0; e[6] = T1; e[7] = T2; e[8] = T3; e[9] = T4;
#pragma unroll
    for (int off = 16; off > 0; off >>= 1)
#pragma unroll
        for (int q = 0; q < NQ; q++)
            e[q] = add2(e[q], __shfl_xor_sync(0xffffffffu, e[q], off));

    // ---- linear head for both samples ----
    if (lane < NC) {
        float eA[NQ], eB[NQ];
#pragma unroll
        for (int q = 0; q < NQ; q++) unpk(e[q], eA[q], eB[q]);
        float oA = __ldg(&bout[lane]);
        float oB = oA;
#pragma unroll
        for (int q = 0; q < NQ; q++) {
            float w = __ldg(&Wout[lane * NQ + q]);
            oA += eA[q] * w;
            oB += eB[q] * w;
        }
        out[(size_t)bA * NC + lane] = oA;
        if (hasB) out[(size_t)bB * NC + lane] = oB;
    }
}

extern "C" void kernel_launch(void* const* d_in, const int* in_sizes, int n_in,
                              void* d_out, int out_size) {
    const float* x = (const float*)d_in[0];        // (B, 1024)
    const float* W_proj = (const float*)d_in[1];   // (10, 1024)
    const float* weights = (const float*)d_in[2];  // (6, 10, 3)
    const float* W_out = (const float*)d_in[3];    // (10, 10)
    const float* b_out = (const float*)d_in[4];    // (10,)
    float* out = (float*)d_out;                    // (B, 10)

    int B = in_sizes[0] / NF;
    int nblk = (B + 7) / 8;
    int npairs = (B + 1) / 2;
    int nblk2 = (npairs + 3) / 4;

    proj_kernel<<<nblk + 1, 256>>>(x, W_proj, weights, B);
    vqc2_kernel<<<nblk2, 128>>>(W_out, b_out, out, B);
}

// round 5
// speedup vs baseline: 1.2546x; 1.2487x over previous
#include <cuda_runtime.h>

#define NQ 10
#define DEPTH 6
#define NF 1024
#define NC 10
#define MAXB 8192

typedef unsigned long long u64;

// Precomputed Rot matrices: [l][q] -> two float4: (u00r,u00i,u01r,u01i),(u10r,u10i,u11r,u11i)
__device__ float4 g_rot4[DEPTH * NQ * 2];
// Precomputed half-angle trig per sample/qubit: (cos, sin)
__device__ float2 g_trig[MAXB * NQ];

// ---------- f32x2 packed helpers ----------
__device__ __forceinline__ u64 pk(float x, float y) {
    u64 u; asm("mov.b64 %0,{%1,%2};" : "=l"(u) : "f"(x), "f"(y)); return u;
}
__device__ __forceinline__ u64 dup2(float x) { return pk(x, x); }
__device__ __forceinline__ void unpk(u64 u, float& x, float& y) {
    asm("mov.b64 {%0,%1},%2;" : "=f"(x), "=f"(y) : "l"(u));
}
__device__ __forceinline__ u64 fma2(u64 a, u64 b, u64 c) {
    u64 d; asm("fma.rn.f32x2 %0,%1,%2,%3;" : "=l"(d) : "l"(a), "l"(b), "l"(c)); return d;
}
__device__ __forceinline__ u64 mul2(u64 a, u64 b) {
    u64 d; asm("mul.rn.f32x2 %0,%1,%2;" : "=l"(d) : "l"(a), "l"(b)); return d;
}
__device__ __forceinline__ u64 add2(u64 a, u64 b) {
    u64 d; asm("add.rn.f32x2 %0,%1,%2;" : "=l"(d) : "l"(a), "l"(b)); return d;
}
__device__ __forceinline__ u64 neg2(u64 a) { return a ^ 0x8000000080000000ULL; }
__device__ __forceinline__ u64 rot32(u64 v) { return (v >> 32) | (v << 32); }

#define LOMASK 0x00000000FFFFFFFFULL
#define HIMASK 0xFFFFFFFF00000000ULL

// ---------- rot matrix build ----------
__device__ __forceinline__ void build_rot_one(const float* __restrict__ w, int t) {
    float phi = w[t * 3 + 0], theta = w[t * 3 + 1], omega = w[t * 3 + 2];
    float c, s;
    sincosf(0.5f * theta, &s, &c);
    float sp, cp, sm, cm;
    sincosf(-0.5f * (phi + omega), &sp, &cp);  // ep
    sincosf(-0.5f * (phi - omega), &sm, &cm);  // em
    g_rot4[t * 2 + 0] = make_float4(cp * c, sp * c, -cm * s, sm * s);   // u00, u01
    g_rot4[t * 2 + 1] = make_float4(cm * s, sm * s, cp * c, -sp * c);   // u10, u11
}

// one warp per sample: 10 dot products (len 1024) -> tanh -> half-angle trig
// last block builds the rot matrices instead.
__global__ __launch_bounds__(256) void proj_kernel(const float* __restrict__ x,
                                                   const float* __restrict__ Wp,
                                                   const float* __restrict__ w, int B) {
    if (blockIdx.x == gridDim.x - 1) {
        int t = threadIdx.x;
        if (t < DEPTH * NQ) build_rot_one(w, t);
        return;
    }
    int warp = threadIdx.x >> 5, lane = threadIdx.x & 31;
    int b = blockIdx.x * 8 + warp;
    if (b >= B) return;
    const float4* xv = (const float4*)(x + (size_t)b * NF);
    float acc[NQ];
#pragma unroll
    for (int q = 0; q < NQ; q++) acc[q] = 0.f;
#pragma unroll
    for (int it = 0; it < 8; it++) {
        float4 xx = xv[it * 32 + lane];
#pragma unroll
        for (int q = 0; q < NQ; q++) {
            float4 ww = __ldg(&((const float4*)(Wp + q * NF))[it * 32 + lane]);
            acc[q] += xx.x * ww.x + xx.y * ww.y + xx.z * ww.z + xx.w * ww.w;
        }
    }
#pragma unroll
    for (int off = 16; off > 0; off >>= 1)
#pragma unroll
        for (int q = 0; q < NQ; q++) acc[q] += __shfl_xor_sync(0xffffffffu, acc[q], off);
    if (lane < NQ) {
        float v = acc[0];
#pragma unroll
        for (int q = 1; q < NQ; q++)
            if (lane == q) v = acc[q];
        float half = tanhf(v) * 0.78539816339744831f;  // (pi/2)/2
        float cc, ss;
        sincosf(half, &ss, &cc);
        g_trig[b * NQ + lane] = make_float2(cc, ss);
    }
}

// Amplitude index m (10 bits): bits0-4 = lane, bits5-8 = reg r (0..15), bit9 = u64 half (lo/hi).
// CNOT ring (range R), all control/target category combinations resolved at compile time.
template <int R>
__device__ __forceinline__ void cnot_layer(u64 (&sr)[16], u64 (&si)[16], int lane) {
#pragma unroll
    for (int i = 0; i < NQ; i++) {
        const int c = i;
        const int t = (i + R) % NQ;
        if (c < 5 && t < 5) {
            // lane ctrl / lane target
            bool ctrl = (lane >> c) & 1;
#pragma unroll
            for (int r = 0; r < 16; r++) {
                u64 pr_ = __shfl_xor_sync(0xffffffffu, sr[r], 1 << t);
                u64 pi_ = __shfl_xor_sync(0xffffffffu, si[r], 1 << t);
                sr[r] = ctrl ? pr_ : sr[r];
                si[r] = ctrl ? pi_ : si[r];
            }
        } else if (c < 5 && t >= 5 && t < 9) {
            // lane ctrl / reg target: predicated u64 swap
            const int tb = 1 << (t - 5);
            bool ctrl = (lane >> c) & 1;
#pragma unroll
            for (int r0 = 0; r0 < 16; r0++)
                if (!(r0 & tb)) {
                    const int r1 = r0 | tb;
                    u64 t0 = sr[r0], t1 = si[r0];
                    sr[r0] = ctrl ? sr[r1] : sr[r0];
                    si[r0] = ctrl ? si[r1] : si[r0];
                    sr[r1] = ctrl ? t0 : sr[r1];
                    si[r1] = ctrl ? t1 : si[r1];
                }
        } else if (c < 5 && t == 9) {
            // lane ctrl / half target: conditional half-swap (rot32)
            bool ctrl = (lane >> c) & 1;
#pragma unroll
            for (int r = 0; r < 16; r++) {
                u64 rr = rot32(sr[r]), ri = rot32(si[r]);
                sr[r] = ctrl ? rr : sr[r];
                si[r] = ctrl ? ri : si[r];
            }
        } else if (c >= 5 && c < 9 && t < 5) {
            // reg ctrl / lane target
            const int cb = 1 << (c - 5);
#pragma unroll
            for (int r = 0; r < 16; r++)
                if (r & cb) {
                    sr[r] = __shfl_xor_sync(0xffffffffu, sr[r], 1 << t);
                    si[r] = __shfl_xor_sync(0xffffffffu, si[r], 1 << t);
                }
        } else if (c >= 5 && c < 9 && t >= 5 && t < 9) {
            // reg ctrl / reg target: free register rename
            const int cb = 1 << (c - 5), tb = 1 << (t - 5);
#pragma unroll
            for (int r0 = 0; r0 < 16; r0++)
                if ((r0 & cb) && !(r0 & tb)) {
                    const int r1 = r0 | tb;
                    u64 tmp = sr[r0]; sr[r0] = sr[r1]; sr[r1] = tmp;
                    tmp = si[r0]; si[r0] = si[r1]; si[r1] = tmp;
                }
        } else if (c >= 5 && c < 9 && t == 9) {
            // reg ctrl / half target: unconditional half-swap on controlled regs
            const int cb = 1 << (c - 5);
#pragma unroll
            for (int r = 0; r < 16; r++)
                if (r & cb) {
                    sr[r] = rot32(sr[r]);
                    si[r] = rot32(si[r]);
                }
        } else if (c == 9 && t < 5) {
            // half ctrl / lane target: permute only hi halves
#pragma unroll
            for (int r = 0; r < 16; r++) {
                u64 pr_ = __shfl_xor_sync(0xffffffffu, sr[r], 1 << t);
                u64 pi_ = __shfl_xor_sync(0xffffffffu, si[r], 1 << t);
                sr[r] = (sr[r] & LOMASK) | (pr_ & HIMASK);
                si[r] = (si[r] & LOMASK) | (pi_ & HIMASK);
            }
        } else {  // c == 9 && t >= 5 && t < 9
            // half ctrl / reg target: swap hi halves between reg pairs
            const int tb = 1 << (t - 5);
#pragma unroll
            for (int r0 = 0; r0 < 16; r0++)
                if (!(r0 & tb)) {
                    const int r1 = r0 | tb;
                    u64 a = sr[r0], b = sr[r1];
                    sr[r0] = (a & LOMASK) | (b & HIMASK);
                    sr[r1] = (b & LOMASK) | (a & HIMASK);
                    a = si[r0]; b = si[r1];
                    si[r0] = (a & LOMASK) | (b & HIMASK);
                    si[r1] = (b & LOMASK) | (a & HIMASK);
                }
        }
    }
}

// one warp per sample; q9 packed into u64 halves -> f32x2 everywhere
__global__ __launch_bounds__(256, 2) void vqc_kernel(const float* __restrict__ Wout,
                                                     const float* __restrict__ bout,
                                                     float* __restrict__ out, int B) {
    const int warp = threadIdx.x >> 5, lane = threadIdx.x & 31;
    const int b = blockIdx.x * 8 + warp;
    if (b >= B) return;

    // ---- init: RY product state ----
    float tc[NQ], ts[NQ];
#pragma unroll
    for (int q = 0; q < NQ; q++) {
        float2 v = g_trig[b * NQ + q];
        tc[q] = v.x;
        ts[q] = v.y;
    }
    float pl = 1.f;
#pragma unroll
    for (int q = 0; q < 5; q++) pl *= ((lane >> q) & 1) ? ts[q] : tc[q];
    u64 sr[16], si[16];
#pragma unroll
    for (int r = 0; r < 16; r++) {
        float base = pl;
#pragma unroll
        for (int j = 0; j < 4; j++) base *= ((r >> j) & 1) ? ts[5 + j] : tc[5 + j];
        sr[r] = pk(base * tc[9], base * ts[9]);
        si[r] = 0ULL;
    }

    // ---- layers ----
#pragma unroll 1
    for (int l = 0; l < DEPTH; l++) {
#pragma unroll
        for (int q = 0; q < NQ; q++) {
            float4 A = __ldg(&g_rot4[(l * NQ + q) * 2]);       // u00, u01
            float4 Bm = __ldg(&g_rot4[(l * NQ + q) * 2 + 1]);  // u10, u11
            if (q >= 5 && q < 9) {
                // reg-bit gate: pure f32x2 on u64 pairs
                u64 c00r = dup2(A.x), c00i = dup2(A.y), c00in = dup2(-A.y);
                u64 c01r = dup2(A.z), c01i = dup2(A.w), c01in = dup2(-A.w);
                u64 c10r = dup2(Bm.x), c10i = dup2(Bm.y), c10in = dup2(-Bm.y);
                u64 c11r = dup2(Bm.z), c11i = dup2(Bm.w), c11in = dup2(-Bm.w);
                const int jb = 1 << (q - 5);
#pragma unroll
                for (int r0 = 0; r0 < 16; r0++)
                    if (!(r0 & jb)) {
                        const int r1 = r0 | jb;
                        u64 a0r = sr[r0], a0i = si[r0];
                        u64 a1r = sr[r1], a1i = si[r1];
                        u64 t;
                        t = mul2(c01in, a1i); t = fma2(c01r, a1r, t); t = fma2(c00in, a0i, t);
                        sr[r0] = fma2(c00r, a0r, t);
                        t = mul2(c01i, a1r); t = fma2(c01r, a1i, t); t = fma2(c00i, a0r, t);
                        si[r0] = fma2(c00r, a0i, t);
                        t = mul2(c11in, a1i); t = fma2(c11r, a1r, t); t = fma2(c10in, a0i, t);
                        sr[r1] = fma2(c10r, a0r, t);
                        t = mul2(c11i, a1r); t = fma2(c11r, a1i, t); t = fma2(c10i, a0r, t);
                        si[r1] = fma2(c10r, a0i, t);
                    }
            } else if (q < 5) {
                // lane-bit gate: u64 shuffle + f32x2 with lane-selected constants
                bool hi = (lane >> q) & 1;
                float car = hi ? Bm.z : A.x, cai = hi ? Bm.w : A.y;
                float cbr = hi ? Bm.x : A.z, cbi = hi ? Bm.y : A.w;
                u64 Car = dup2(car), Cai = dup2(cai), Cain = dup2(-cai);
                u64 Cbr = dup2(cbr), Cbi = dup2(cbi), Cbin = dup2(-cbi);
#pragma unroll
                for (int r = 0; r < 16; r++) {
                    u64 pr_ = __shfl_xor_sync(0xffffffffu, sr[r], 1 << q);
                    u64 pi_ = __shfl_xor_sync(0xffffffffu, si[r], 1 << q);
                    u64 mr = sr[r], mi = si[r];
                    u64 t;
                    t = mul2(Cbin, pi_); t = fma2(Cbr, pr_, t); t = fma2(Cain, mi, t);
                    sr[r] = fma2(Car, mr, t);
                    t = mul2(Cbi, pr_); t = fma2(Cbr, pi_, t); t = fma2(Cai, mr, t);
                    si[r] = fma2(Car, mi, t);
                }
            } else {
                // q == 9: half-bit gate. lo lane computes n0, hi lane computes n1,
                // constants packed (row0, row1); result lands pre-packed.
                u64 K0r = pk(A.x, Bm.x), K0i = pk(A.y, Bm.y), K0in = pk(-A.y, -Bm.y);
                u64 K1r = pk(A.z, Bm.z), K1i = pk(A.w, Bm.w), K1in = pk(-A.w, -Bm.w);
#pragma unroll
                for (int r = 0; r < 16; r++) {
                    float a0r, a1r, a0i, a1i;
                    unpk(sr[r], a0r, a1r);
                    unpk(si[r], a0i, a1i);
                    u64 d0r = dup2(a0r), d1r = dup2(a1r);
                    u64 d0i = dup2(a0i), d1i = dup2(a1i);
                    u64 t;
                    t = mul2(K1in, d1i); t = fma2(K1r, d1r, t); t = fma2(K0in, d0i, t);
                    sr[r] = fma2(K0r, d0r, t);
                    t = mul2(K1i, d1r); t = fma2(K1r, d1i, t); t = fma2(K0i, d0r, t);
                    si[r] = fma2(K0r, d0i, t);
                }
            }
        }
        switch (l) {
            case 0: cnot_layer<1>(sr, si, lane); break;
            case 1: cnot_layer<2>(sr, si, lane); break;
            case 2: cnot_layer<3>(sr, si, lane); break;
            case 3: cnot_layer<4>(sr, si, lane); break;
            case 4: cnot_layer<5>(sr, si, lane); break;
            default: cnot_layer<6>(sr, si, lane); break;
        }
    }

    // ---- Z expvals ----
    u64 S2 = 0ULL, U0 = 0ULL, U1 = 0ULL, U2 = 0ULL, U3 = 0ULL;
#pragma unroll
    for (int r = 0; r < 16; r++) {
        u64 p = fma2(sr[r], sr[r], mul2(si[r], si[r]));
        u64 np = neg2(p);
        S2 = add2(S2, p);
        U0 = add2(U0, (r & 1) ? np : p);
        U1 = add2(U1, (r & 2) ? np : p);
        U2 = add2(U2, (r & 4) ? np : p);
        U3 = add2(U3, (r & 8) ? np : p);
    }
    float slo, shi;
    unpk(S2, slo, shi);
    float Stot = slo + shi;
    float e[NQ];
#pragma unroll
    for (int q = 0; q < 5; q++) e[q] = ((lane >> q) & 1) ? -Stot : Stot;
    {
        float lo, hi;
        unpk(U0, lo, hi); e[5] = lo + hi;
        unpk(U1, lo, hi); e[6] = lo + hi;
        unpk(U2, lo, hi); e[7] = lo + hi;
        unpk(U3, lo, hi); e[8] = lo + hi;
        e[9] = slo - shi;
    }
#pragma unroll
    for (int off = 16; off > 0; off >>= 1)
#pragma unroll
        for (int q = 0; q < NQ; q++) e[q] += __shfl_xor_sync(0xffffffffu, e[q], off);

    // ---- linear head ----
    if (lane < NC) {
        float o = __ldg(&bout[lane]);
#pragma unroll
        for (int q = 0; q < NQ; q++) o += e[q] * __ldg(&Wout[lane * NQ + q]);
        out[(size_t)b * NC + lane] = o;
    }
}

extern "C" void kernel_launch(void* const* d_in, const int* in_sizes, int n_in,
                              void* d_out, int out_size) {
    const float* x = (const float*)d_in[0];        // (B, 1024)
    const float* W_proj = (const float*)d_in[1];   // (10, 1024)
    const float* weights = (const float*)d_in[2];  // (6, 10, 3)
    const float* W_out = (const float*)d_in[3];    // (10, 10)
    const float* b_out = (const float*)d_in[4];    // (10,)
    float* out = (float*)d_out;                    // (B, 10)

    int B = in_sizes[0] / NF;
    int nblk = (B + 7) / 8;

    proj_kernel<<<nblk + 1, 256>>>(x, W_proj, weights, B);
    vqc_kernel<<<nblk, 256>>>(W_out, b_out, out, B);
}

// round 6
// speedup vs baseline: 1.3654x; 1.0883x over previous
#include <cuda_runtime.h>

#define NQ 10
#define DEPTH 6
#define NF 1024
#define NC 10

typedef unsigned long long u64;

// ---------- f32x2 packed helpers ----------
__device__ __forceinline__ u64 pk(float x, float y) {
    u64 u; asm("mov.b64 %0,{%1,%2};" : "=l"(u) : "f"(x), "f"(y)); return u;
}
__device__ __forceinline__ u64 dup2(float x) { return pk(x, x); }
__device__ __forceinline__ void unpk(u64 u, float& x, float& y) {
    asm("mov.b64 {%0,%1},%2;" : "=f"(x), "=f"(y) : "l"(u));
}
__device__ __forceinline__ u64 fma2(u64 a, u64 b, u64 c) {
    u64 d; asm("fma.rn.f32x2 %0,%1,%2,%3;" : "=l"(d) : "l"(a), "l"(b), "l"(c)); return d;
}
__device__ __forceinline__ u64 mul2(u64 a, u64 b) {
    u64 d; asm("mul.rn.f32x2 %0,%1,%2;" : "=l"(d) : "l"(a), "l"(b)); return d;
}
__device__ __forceinline__ u64 add2(u64 a, u64 b) {
    u64 d; asm("add.rn.f32x2 %0,%1,%2;" : "=l"(d) : "l"(a), "l"(b)); return d;
}
__device__ __forceinline__ u64 neg2(u64 a) { return a ^ 0x8000000080000000ULL; }
__device__ __forceinline__ u64 rot32(u64 v) { return (v >> 32) | (v << 32); }

#define LOMASK 0x00000000FFFFFFFFULL
#define HIMASK 0xFFFFFFFF00000000ULL
#define FULLM 0xffffffffu

// Amplitude index m (10 bits): bits0-4 = lane, bits5-8 = reg r (0..15), bit9 = u64 half.
// CNOT ring (range R); all category combinations resolved at compile time.
template <int R>
__device__ __forceinline__ void cnot_layer(u64 (&sr)[16], u64 (&si)[16], int lane) {
#pragma unroll
    for (int i = 0; i < NQ; i++) {
        const int c = i;
        const int t = (i + R) % NQ;
        if (c < 5 && t < 5) {
            // lane ctrl / lane target: variable-source shuffle (no selects)
            bool ctrl = (lane >> c) & 1;
            int src = ctrl ? (lane ^ (1 << t)) : lane;
#pragma unroll
            for (int r = 0; r < 16; r++) {
                sr[r] = __shfl_sync(FULLM, sr[r], src);
                si[r] = __shfl_sync(FULLM, si[r], src);
            }
        } else if (c < 5 && t >= 5 && t < 9) {
            // lane ctrl / reg target: predicated u64 swap
            const int tb = 1 << (t - 5);
            bool ctrl = (lane >> c) & 1;
#pragma unroll
            for (int r0 = 0; r0 < 16; r0++)
                if (!(r0 & tb)) {
                    const int r1 = r0 | tb;
                    u64 t0 = sr[r0], t1 = si[r0];
                    sr[r0] = ctrl ? sr[r1] : sr[r0];
                    si[r0] = ctrl ? si[r1] : si[r0];
                    sr[r1] = ctrl ? t0 : sr[r1];
                    si[r1] = ctrl ? t1 : si[r1];
                }
        } else if (c < 5 && t == 9) {
            // lane ctrl / half target: conditional half-swap
            bool ctrl = (lane >> c) & 1;
#pragma unroll
            for (int r = 0; r < 16; r++) {
                u64 rr = rot32(sr[r]), ri = rot32(si[r]);
                sr[r] = ctrl ? rr : sr[r];
                si[r] = ctrl ? ri : si[r];
            }
        } else if (c >= 5 && c < 9 && t < 5) {
            // reg ctrl / lane target
            const int cb = 1 << (c - 5);
#pragma unroll
            for (int r = 0; r < 16; r++)
                if (r & cb) {
                    sr[r] = __shfl_xor_sync(FULLM, sr[r], 1 << t);
                    si[r] = __shfl_xor_sync(FULLM, si[r], 1 << t);
                }
        } else if (c >= 5 && c < 9 && t >= 5 && t < 9) {
            // reg ctrl / reg target: free register rename
            const int cb = 1 << (c - 5), tb = 1 << (t - 5);
#pragma unroll
            for (int r0 = 0; r0 < 16; r0++)
                if ((r0 & cb) && !(r0 & tb)) {
                    const int r1 = r0 | tb;
                    u64 tmp = sr[r0]; sr[r0] = sr[r1]; sr[r1] = tmp;
                    tmp = si[r0]; si[r0] = si[r1]; si[r1] = tmp;
                }
        } else if (c >= 5 && c < 9 && t == 9) {
            // reg ctrl / half target
            const int cb = 1 << (c - 5);
#pragma unroll
            for (int r = 0; r < 16; r++)
                if (r & cb) {
                    sr[r] = rot32(sr[r]);
                    si[r] = rot32(si[r]);
                }
        } else if (c == 9 && t < 5) {
            // half ctrl / lane target: permute only hi halves
#pragma unroll
            for (int r = 0; r < 16; r++) {
                u64 pr_ = __shfl_xor_sync(FULLM, sr[r], 1 << t);
                u64 pi_ = __shfl_xor_sync(FULLM, si[r], 1 << t);
                sr[r] = (sr[r] & LOMASK) | (pr_ & HIMASK);
                si[r] = (si[r] & LOMASK) | (pi_ & HIMASK);
            }
        } else {  // c == 9 && t >= 5 && t < 9: swap hi halves between reg pairs
            const int tb = 1 << (t - 5);
#pragma unroll
            for (int r0 = 0; r0 < 16; r0++)
                if (!(r0 & tb)) {
                    const int r1 = r0 | tb;
                    u64 a = sr[r0], b = sr[r1];
                    sr[r0] = (a & LOMASK) | (b & HIMASK);
                    sr[r1] = (b & LOMASK) | (a & HIMASK);
                    a = si[r0]; b = si[r1];
                    si[r0] = (a & LOMASK) | (b & HIMASK);
                    si[r1] = (b & LOMASK) | (a & HIMASK);
                }
        }
    }
}

// Fully fused: SMEM rot build + per-warp projection + register-resident VQC sim + head.
__global__ __launch_bounds__(256, 2) void fused_kernel(
    const float* __restrict__ x, const float* __restrict__ Wp,
    const float* __restrict__ w, const float* __restrict__ Wout,
    const float* __restrict__ bout, float* __restrict__ out, int B) {
    // SU(2) gate table: srot[g] = (alpha_r, alpha_i, beta_r, beta_i)
    __shared__ float4 srot[DEPTH * NQ];
    const int tid = threadIdx.x;
    if (tid < DEPTH * NQ) {
        float phi = w[tid * 3 + 0], theta = w[tid * 3 + 1], omega = w[tid * 3 + 2];
        float c, s;
        sincosf(0.5f * theta, &s, &c);
        float sp, cp, sm, cm;
        sincosf(-0.5f * (phi + omega), &sp, &cp);  // ep
        sincosf(-0.5f * (phi - omega), &sm, &cm);  // em
        // alpha = ep*c ; beta = -conj(em)*s
        srot[tid] = make_float4(cp * c, sp * c, -cm * s, sm * s);
    }
    __syncthreads();

    const int warp = tid >> 5, lane = tid & 31;
    const int b = blockIdx.x * 8 + warp;
    if (b >= B) return;

    // ---- projection: 10 dots of x[b] with W_proj rows -> tanh -> half-angle trig ----
    float tc[NQ], ts[NQ];
    {
        const float4* xv = (const float4*)(x + (size_t)b * NF);
        float acc[NQ];
#pragma unroll
        for (int q = 0; q < NQ; q++) acc[q] = 0.f;
#pragma unroll
        for (int it = 0; it < 8; it++) {
            float4 xx = xv[it * 32 + lane];
#pragma unroll
            for (int q = 0; q < NQ; q++) {
                float4 ww = __ldg(&((const float4*)(Wp + q * NF))[it * 32 + lane]);
                acc[q] += xx.x * ww.x + xx.y * ww.y + xx.z * ww.z + xx.w * ww.w;
            }
        }
#pragma unroll
        for (int off = 16; off > 0; off >>= 1)
#pragma unroll
            for (int q = 0; q < NQ; q++) acc[q] += __shfl_xor_sync(FULLM, acc[q], off);
        float myc = 0.f, mys = 0.f;
        if (lane < NQ) {
            float v = acc[0];
#pragma unroll
            for (int q = 1; q < NQ; q++)
                if (lane == q) v = acc[q];
            float half = tanhf(v) * 0.78539816339744831f;  // (pi/2)/2
            sincosf(half, &mys, &myc);
        }
#pragma unroll
        for (int q = 0; q < NQ; q++) {
            tc[q] = __shfl_sync(FULLM, myc, q);
            ts[q] = __shfl_sync(FULLM, mys, q);
        }
    }

    // ---- init: RY product state ----
    float pl = 1.f;
#pragma unroll
    for (int q = 0; q < 5; q++) pl *= ((lane >> q) & 1) ? ts[q] : tc[q];
    u64 sr[16], si[16];
#pragma unroll
    for (int r = 0; r < 16; r++) {
        float base = pl;
#pragma unroll
        for (int j = 0; j < 4; j++) base *= ((r >> j) & 1) ? ts[5 + j] : tc[5 + j];
        sr[r] = pk(base * tc[9], base * ts[9]);
        si[r] = 0ULL;
    }

    // ---- layers ----
#pragma unroll 1
    for (int l = 0; l < DEPTH; l++) {
#pragma unroll
        for (int q = 0; q < NQ; q++) {
            float4 G = srot[l * NQ + q];  // (ar, ai, br, bi)
            if (q >= 5 && q < 9) {
                // reg-bit gate, SU(2): n0 = a*x0 + b*x1 ; n1 = -conj(b)*x0 + conj(a)*x1
                u64 Ar = dup2(G.x), Ai = dup2(G.y), Ain = dup2(-G.y);
                u64 Br = dup2(G.z), Brn = dup2(-G.z);
                u64 Bi = dup2(G.w), Bin = dup2(-G.w);
                const int jb = 1 << (q - 5);
#pragma unroll
                for (int r0 = 0; r0 < 16; r0++)
                    if (!(r0 & jb)) {
                        const int r1 = r0 | jb;
                        u64 a0r = sr[r0], a0i = si[r0];
                        u64 a1r = sr[r1], a1i = si[r1];
                        u64 t;
                        t = mul2(Bin, a1i); t = fma2(Br, a1r, t); t = fma2(Ain, a0i, t);
                        sr[r0] = fma2(Ar, a0r, t);
                        t = mul2(Bi, a1r); t = fma2(Br, a1i, t); t = fma2(Ai, a0r, t);
                        si[r0] = fma2(Ar, a0i, t);
                        t = mul2(Bin, a0i); t = fma2(Brn, a0r, t); t = fma2(Ai, a1i, t);
                        sr[r1] = fma2(Ar, a1r, t);
                        t = mul2(Bi, a0r); t = fma2(Brn, a0i, t); t = fma2(Ain, a1r, t);
                        si[r1] = fma2(Ar, a1i, t);
                    }
            } else if (q < 5) {
                // lane-bit gate: mine-coef = (ar, +/-ai), partner-coef = (+/-br, bi)
                bool hi = (lane >> q) & 1;
                float sai = hi ? -G.y : G.y;
                float sbr = hi ? -G.z : G.z;
                u64 Ar = dup2(G.x), Sai = dup2(sai), Sain = dup2(-sai);
                u64 Sbr = dup2(sbr), Bi = dup2(G.w), Bin = dup2(-G.w);
#pragma unroll
                for (int r = 0; r < 16; r++) {
                    u64 pr_ = __shfl_xor_sync(FULLM, sr[r], 1 << q);
                    u64 pi_ = __shfl_xor_sync(FULLM, si[r], 1 << q);
                    u64 mr = sr[r], mi = si[r];
                    u64 t;
                    t = mul2(Bin, pi_); t = fma2(Sbr, pr_, t); t = fma2(Sain, mi, t);
                    sr[r] = fma2(Ar, mr, t);
                    t = mul2(Bi, pr_); t = fma2(Sbr, pi_, t); t = fma2(Sai, mr, t);
                    si[r] = fma2(Ar, mi, t);
                }
            } else {
                // q == 9 (half bit): n = K0 (.) s + K1 (.) rot32(s), complex elementwise
                // K0 = (u00, u11) = (a, conj a); K1 = (u01, u10) = (b, -conj b)
                u64 K0r = dup2(G.x), K0i = pk(G.y, -G.y), K0in = pk(-G.y, G.y);
                u64 K1r = pk(G.z, -G.z), K1i = dup2(G.w), K1in = dup2(-G.w);
#pragma unroll
                for (int r = 0; r < 16; r++) {
                    u64 mr = sr[r], mi = si[r];
                    u64 tr = rot32(mr), ti = rot32(mi);
                    u64 t;
                    t = mul2(K1in, ti); t = fma2(K1r, tr, t); t = fma2(K0in, mi, t);
                    sr[r] = fma2(K0r, mr, t);
                    t = mul2(K1i, tr); t = fma2(K1r, ti, t); t = fma2(K0i, mr, t);
                    si[r] = fma2(K0r, mi, t);
                }
            }
        }
        switch (l) {
            case 0: cnot_layer<1>(sr, si, lane); break;
            case 1: cnot_layer<2>(sr, si, lane); break;
            case 2: cnot_layer<3>(sr, si, lane); break;
            case 3: cnot_layer<4>(sr, si, lane); break;
            case 4: cnot_layer<5>(sr, si, lane); break;
            default: cnot_layer<6>(sr, si, lane); break;
        }
    }

    // ---- Z expvals ----
    u64 S2 = 0ULL, U0 = 0ULL, U1 = 0ULL, U2 = 0ULL, U3 = 0ULL;
#pragma unroll
    for (int r = 0; r < 16; r++) {
        u64 p = fma2(sr[r], sr[r], mul2(si[r], si[r]));
        u64 np = neg2(p);
        S2 = add2(S2, p);
        U0 = add2(U0, (r & 1) ? np : p);
        U1 = add2(U1, (r & 2) ? np : p);
        U2 = add2(U2, (r & 4) ? np : p);
        U3 = add2(U3, (r & 8) ? np : p);
    }
    float slo, shi;
    unpk(S2, slo, shi);
    float Stot = slo + shi;
    float e[NQ];
#pragma unroll
    for (int q = 0; q < 5; q++) e[q] = ((lane >> q) & 1) ? -Stot : Stot;
    {
        float lo, hi;
        unpk(U0, lo, hi); e[5] = lo + hi;
        unpk(U1, lo, hi); e[6] = lo + hi;
        unpk(U2, lo, hi); e[7] = lo + hi;
        unpk(U3, lo, hi); e[8] = lo + hi;
        e[9] = slo - shi;
    }
#pragma unroll
    for (int off = 16; off > 0; off >>= 1)
#pragma unroll
        for (int q = 0; q < NQ; q++) e[q] += __shfl_xor_sync(FULLM, e[q], off);

    // ---- linear head ----
    if (lane < NC) {
        float o = __ldg(&bout[lane]);
#pragma unroll
        for (int q = 0; q < NQ; q++) o += e[q] * __ldg(&Wout[lane * NQ + q]);
        out[(size_t)b * NC + lane] = o;
    }
}

extern "C" void kernel_launch(void* const* d_in, const int* in_sizes, int n_in,
                              void* d_out, int out_size) {
    const float* x = (const float*)d_in[0];        // (B, 1024)
    const float* W_proj = (const float*)d_in[1];   // (10, 1024)
    const float* weights = (const float*)d_in[2];  // (6, 10, 3)
    const float* W_out = (const float*)d_in[3];    // (10, 10)
    const float* b_out = (const float*)d_in[4];    // (10,)
    float* out = (float*)d_out;                    // (B, 10)

    int B = in_sizes[0] / NF;
    int nblk = (B + 7) / 8;

    fused_kernel<<<nblk, 256>>>(x, W_proj, weights, W_out, b_out, out, B);
}